// round 10
// baseline (speedup 1.0000x reference)
#include <cuda_runtime.h>
#include <cuda_fp16.h>
#include <math.h>
#include <stdint.h>

#define NN 50000
#define EE 1600000
#define D 128
#define DAGG 384
#define DCAT 1152
#define CAP 128
#define AVG_D_LOG_F 3.4965075614664802f

// ---------------- static scratch --------------------------------------------
__device__ int g_cnt[NN];
__device__ int g_srcl[(size_t)NN * CAP];
__device__ float g_e1[NN];
__device__ __align__(16) __half g_hh[(size_t)NN * D];       // h in fp16
__device__ __align__(16) __half g_aggh[(size_t)NN * DAGG];  // agg fp16 [N,384]
__device__ __align__(16) __half g_Wh[(size_t)DCAT * D];     // W in fp16 [1152,128]

// ---------------- helpers ---------------------------------------------------
__device__ __forceinline__ float4 h4conv(uint2 u) {
    __half2 a = *reinterpret_cast<__half2*>(&u.x);
    __half2 b = *reinterpret_cast<__half2*>(&u.y);
    float2 fa = __half22float2(a);
    float2 fb = __half22float2(b);
    return make_float4(fa.x, fa.y, fb.x, fb.y);
}

__device__ __forceinline__ uint2 pack4(float4 v) {
    uint2 r;
    __half2 lo = __floats2half2_rn(v.x, v.y);
    __half2 hi = __floats2half2_rn(v.z, v.w);
    r.x = *reinterpret_cast<uint32_t*>(&lo);
    r.y = *reinterpret_cast<uint32_t*>(&hi);
    return r;
}

__device__ __forceinline__ void mma_f16(float* c, const uint32_t* a,
                                        uint32_t b0, uint32_t b1) {
    asm volatile(
        "mma.sync.aligned.m16n8k16.row.col.f32.f16.f16.f32 "
        "{%0,%1,%2,%3}, {%4,%5,%6,%7}, {%8,%9}, {%0,%1,%2,%3};\n"
        : "+f"(c[0]), "+f"(c[1]), "+f"(c[2]), "+f"(c[3])
        : "r"(a[0]), "r"(a[1]), "r"(a[2]), "r"(a[3]), "r"(b0), "r"(b1));
}

__device__ __forceinline__ void ldm_x4(uint32_t* r, uint32_t addr) {
    asm volatile("ldmatrix.sync.aligned.m8n8.x4.shared.b16 {%0,%1,%2,%3}, [%4];"
                 : "=r"(r[0]), "=r"(r[1]), "=r"(r[2]), "=r"(r[3]) : "r"(addr));
}

__device__ __forceinline__ void ldm_x4t(uint32_t* r, uint32_t addr) {
    asm volatile("ldmatrix.sync.aligned.m8n8.x4.trans.shared.b16 {%0,%1,%2,%3}, [%4];"
                 : "=r"(r[0]), "=r"(r[1]), "=r"(r[2]), "=r"(r[3]) : "r"(addr));
}

__device__ __forceinline__ void cp16(uint32_t smem_addr, const void* gptr) {
    asm volatile("cp.async.cg.shared.global [%0], [%1], 16;\n"
                 :: "r"(smem_addr), "l"(gptr));
}

// ---------------- kernel 1: fused prep + bucket fill -------------------------
#define FILLB 1563
#define HCONVB 3125
#define WCONVB 576
#define E1B 196
#define PREPGRID (FILLB + HCONVB + WCONVB + E1B)

__global__ void k_prepfill(const int4* __restrict__ src4, const int4* __restrict__ dst4,
                           const float* __restrict__ h, const float* __restrict__ eig,
                           const float* __restrict__ W) {
    int b = blockIdx.x;
    int t = threadIdx.x;
    if (b < FILLB) {
        int i = b * 256 + t;
        if (i >= EE / 4) return;
        int4 d = dst4[i];
        int4 s = src4[i];
        int p0 = atomicAdd(&g_cnt[d.x], 1);
        int p1 = atomicAdd(&g_cnt[d.y], 1);
        int p2 = atomicAdd(&g_cnt[d.z], 1);
        int p3 = atomicAdd(&g_cnt[d.w], 1);
        g_srcl[(size_t)d.x * CAP + p0] = s.x;
        g_srcl[(size_t)d.y * CAP + p1] = s.y;
        g_srcl[(size_t)d.z * CAP + p2] = s.z;
        g_srcl[(size_t)d.w * CAP + p3] = s.w;
    } else if (b < FILLB + HCONVB) {
        int i = (b - FILLB) * 256 + t;
        const float4* h4 = (const float4*)h;
        uint2* o = (uint2*)g_hh;
#pragma unroll
        for (int r = 0; r < 2; r++) {
            int idx = i + r * 800000;
            float4 v = h4[idx];
            o[idx] = pack4(v);
        }
    } else if (b < FILLB + HCONVB + WCONVB) {
        int idx = (b - FILLB - HCONVB) * 256 + t;
        if (idx < DCAT * D)
            g_Wh[idx] = __float2half(W[idx]);
    } else {
        int idx = (b - FILLB - HCONVB - WCONVB) * 256 + t;
        if (idx < NN) g_e1[idx] = eig[(size_t)idx * 4];
    }
}

// ---------------- kernel 2: warp-per-node reduce (8-edge ILP) ----------------
__global__ __launch_bounds__(256) void k_reduce() {
    int wid = threadIdx.x >> 5;
    int lane = threadIdx.x & 31;
    int node = blockIdx.x * 8 + wid;
    if (node >= NN) return;
    int deg = g_cnt[node];
    size_t base = (size_t)node * CAP;
    float e1d = g_e1[node];
    const uint2* h2 = reinterpret_cast<const uint2*>(g_hh);

    float sx = 0.f, sy = 0.f, sz = 0.f, sw = 0.f;
    float mxx = -3.402823466e38f, mxy = mxx, mxz = mxx, mxw = mxx;
    float dx = 0.f, dy = 0.f, dz = 0.f, dw = 0.f;
    float wsum = 0.f;

    int j = 0;
    for (; j + 8 <= deg; j += 8) {
        int s[8];
        float w[8];
        uint2 u[8];
#pragma unroll
        for (int q = 0; q < 8; q++) s[q] = g_srcl[base + j + q];
#pragma unroll
        for (int q = 0; q < 8; q++) u[q] = h2[(size_t)s[q] * 32 + lane];
#pragma unroll
        for (int q = 0; q < 8; q++) w[q] = fabsf(g_e1[s[q]] - e1d);
#pragma unroll
        for (int q = 0; q < 8; q++) {
            float4 v = h4conv(u[q]);
            sx += v.x; sy += v.y; sz += v.z; sw += v.w;
            mxx = fmaxf(mxx, v.x); mxy = fmaxf(mxy, v.y);
            mxz = fmaxf(mxz, v.z); mxw = fmaxf(mxw, v.w);
            dx = fmaf(w[q], v.x, dx); dy = fmaf(w[q], v.y, dy);
            dz = fmaf(w[q], v.z, dz); dw = fmaf(w[q], v.w, dw);
            wsum += w[q];
        }
    }
    for (; j < deg; j++) {
        int s0 = g_srcl[base + j];
        float w0 = fabsf(g_e1[s0] - e1d);
        float4 v0 = h4conv(h2[(size_t)s0 * 32 + lane]);
        sx += v0.x; sy += v0.y; sz += v0.z; sw += v0.w;
        mxx = fmaxf(mxx, v0.x); mxy = fmaxf(mxy, v0.y);
        mxz = fmaxf(mxz, v0.z); mxw = fmaxf(mxw, v0.w);
        dx = fmaf(w0, v0.x, dx); dy = fmaf(w0, v0.y, dy);
        dz = fmaf(w0, v0.z, dz); dw = fmaf(w0, v0.w, dw);
        wsum += w0;
    }

    float invd = 1.f / (float)(deg > 0 ? deg : 1);
    float invw = 1.f / (wsum + 1e-30f);
    if (deg == 0) { mxx = 0.f; mxy = 0.f; mxz = 0.f; mxw = 0.f; }

    uint2* o = reinterpret_cast<uint2*>(g_aggh) + (size_t)node * 96;
    o[lane]      = pack4(make_float4(sx * invd, sy * invd, sz * invd, sw * invd));
    o[32 + lane] = pack4(make_float4(mxx, mxy, mxz, mxw));
    o[64 + lane] = pack4(make_float4(dx * invw, dy * invw, dz * invw, dw * invw));
}

// ---------------- kernel 3: triple-accumulator GEMM + fp32 epilogue ----------
// Tile: BM=128 x BN=32; warp tile 16x32; 8 warps; 3 accumulator groups.
// out[r,c] = epi( c0 + amp(r)*c1 + att(r)*c2 ), cg = agg @ W_g.
#define BM 128
#define BN 32
#define BK 32
#define NKT (DAGG / BK)  // 12
#define NSTG 3
// byte layout: As 3 stages x (128 rows x 40 halfs x 2B = 10240)
//              Bs 3 stages x (3 g x 32 rows x 40 halfs x 2B = 7680)
#define A_STAGE 10240
#define B_STAGE 7680
#define BS_OFF (3 * A_STAGE)                  // 30720
#define COEF_OFF (BS_OFF + 3 * B_STAGE)       // 53760
#define SMEM_BYTES (COEF_OFF + 3 * 128 * 4)   // 55296

__global__ __launch_bounds__(256, 2) void k_gemm(
    const float* __restrict__ h, const float* __restrict__ snorm,
    const float* __restrict__ bias, const float* __restrict__ gamma,
    const float* __restrict__ beta, const float* __restrict__ mean,
    const float* __restrict__ var, float* __restrict__ out) {
    extern __shared__ char smc[];
    uint32_t sb = (uint32_t)__cvta_generic_to_shared(smc);
    float* samp = (float*)(smc + COEF_OFF);
    float* satt = samp + BM;
    float* ssn = satt + BM;

    int tid = threadIdx.x;
    int wid = tid >> 5;
    int lane = tid & 31;
    int t = lane & 3;
    int gid = lane >> 2;
    int rowBlock = (blockIdx.x >> 2) * BM;
    int colBlock = (blockIdx.x & 3) * BN;

    // per-row scaler coefficients
    for (int i = tid; i < BM; i += 256) {
        int r = rowBlock + i;
        float amp = 0.f, att = 0.f, sn = 0.f;
        if (r < NN) {
            int deg = g_cnt[r];
            float logD = logf((float)deg + 1.0f);
            amp = logD * (1.0f / AVG_D_LOG_F);
            att = AVG_D_LOG_F / fmaxf(logD, 1e-6f);
            sn = snorm[r];
        }
        samp[i] = amp;
        satt[i] = att;
        ssn[i] = sn;
    }

    // A cp lanes: 512 chunks of 16B (128 rows x 4); 2 per thread
    int a_row0 = tid >> 2, a_chk = tid & 3;
    int ar0 = rowBlock + a_row0; if (ar0 > NN - 1) ar0 = NN - 1;
    int ar1 = rowBlock + a_row0 + 64; if (ar1 > NN - 1) ar1 = NN - 1;
    const __half* a_src0 = g_aggh + (size_t)ar0 * DAGG + a_chk * 8;
    const __half* a_src1 = g_aggh + (size_t)ar1 * DAGG + a_chk * 8;
    uint32_t a_dst0 = sb + a_row0 * 80 + a_chk * 16;
    uint32_t a_dst1 = a_dst0 + 64 * 80;

    // B cp lanes: 384 chunks over [3 g][32 rows][4 chunks]; idx = tid, tid+256(<384)
    int bg0 = tid >> 7, br0 = (tid & 127) >> 2, bc0 = (tid & 3);
    const __half* b_src0 = g_Wh + ((size_t)bg0 * DAGG + br0) * D + colBlock + bc0 * 8;
    uint32_t b_dst0 = sb + BS_OFF + bg0 * 2560 + br0 * 80 + bc0 * 16;
    int idx1 = tid + 256;
    int bg1 = idx1 >> 7, br1 = (idx1 & 127) >> 2, bc1 = (idx1 & 3);
    const __half* b_src1 = g_Wh + ((size_t)bg1 * DAGG + br1) * D + colBlock + bc1 * 8;
    uint32_t b_dst1 = sb + BS_OFF + bg1 * 2560 + br1 * 80 + bc1 * 16;
    bool bdo1 = idx1 < 384;

    float c[3][4][4];
#pragma unroll
    for (int g = 0; g < 3; g++)
#pragma unroll
        for (int nt = 0; nt < 4; nt++)
#pragma unroll
            for (int k = 0; k < 4; k++) c[g][nt][k] = 0.f;

    // prologue: prefetch kt=0, kt=1
#pragma unroll
    for (int pk = 0; pk < 2; pk++) {
        size_t koff = (size_t)pk * BK;
        cp16(a_dst0 + pk * A_STAGE, a_src0 + koff);
        cp16(a_dst1 + pk * A_STAGE, a_src1 + koff);
        cp16(b_dst0 + pk * B_STAGE, b_src0 + koff * D);
        if (bdo1) cp16(b_dst1 + pk * B_STAGE, b_src1 + koff * D);
        asm volatile("cp.async.commit_group;\n");
    }

    __syncthreads();  // coef arrays visible

    // ldmatrix bases (stage 0)
    uint32_t a_lm = sb + (wid * 16 + (lane & 15)) * 80 + ((lane >> 4) << 4);
    uint32_t b_lm = sb + BS_OFF + (lane & 15) * 80 + ((lane >> 4) << 4);

    int buf = 0;
    for (int kt = 0; kt < NKT; kt++) {
        if (kt + 1 < NKT) {
            asm volatile("cp.async.wait_group 1;\n");
        } else {
            asm volatile("cp.async.wait_group 0;\n");
        }
        __syncthreads();

        if (kt + 2 < NKT) {
            int nb = buf + 2; if (nb >= NSTG) nb -= NSTG;
            size_t koff = (size_t)(kt + 2) * BK;
            cp16(a_dst0 + nb * A_STAGE, a_src0 + koff);
            cp16(a_dst1 + nb * A_STAGE, a_src1 + koff);
            cp16(b_dst0 + nb * B_STAGE, b_src0 + koff * D);
            if (bdo1) cp16(b_dst1 + nb * B_STAGE, b_src1 + koff * D);
            asm volatile("cp.async.commit_group;\n");
        }

        uint32_t a_base = a_lm + buf * A_STAGE;
        uint32_t b_base = b_lm + buf * B_STAGE;
#pragma unroll
        for (int ks = 0; ks < 2; ks++) {
            uint32_t a[4];
            ldm_x4(a, a_base + ks * 32);
#pragma unroll
            for (int g = 0; g < 3; g++) {
                uint32_t b0[4], b1[4];
                ldm_x4t(b0, b_base + g * 2560 + ks * 1280);
                ldm_x4t(b1, b_base + g * 2560 + ks * 1280 + 32);
                mma_f16(c[g][0], a, b0[0], b0[1]);
                mma_f16(c[g][1], a, b0[2], b0[3]);
                mma_f16(c[g][2], a, b1[0], b1[1]);
                mma_f16(c[g][3], a, b1[2], b1[3]);
            }
        }
        __syncthreads();
        buf++; if (buf >= NSTG) buf = 0;
    }

    // fp32 epilogue: combine groups, bias, graphnorm, BN, relu, residual
    int rl0 = wid * 16 + gid;
    float amp0 = samp[rl0], att0 = satt[rl0], sn0 = ssn[rl0];
    float amp1 = samp[rl0 + 8], att1 = satt[rl0 + 8], sn1 = ssn[rl0 + 8];
    int r0 = rowBlock + rl0;
    int r1 = r0 + 8;
#pragma unroll
    for (int nt = 0; nt < 4; nt++) {
        int col = colBlock + nt * 8 + 2 * t;
        float2 bi = *(const float2*)(bias + col);
        float2 mn = *(const float2*)(mean + col);
        float2 vr = *(const float2*)(var + col);
        float2 gm = *(const float2*)(gamma + col);
        float2 bt = *(const float2*)(beta + col);
        float sc0 = rsqrtf(vr.x + 1e-5f) * gm.x;
        float sc1 = rsqrtf(vr.y + 1e-5f) * gm.y;
        float sh0 = bt.x - mn.x * sc0;
        float sh1 = bt.y - mn.y * sc1;
        if (r0 < NN) {
            float v0 = c[0][nt][0] + amp0 * c[1][nt][0] + att0 * c[2][nt][0];
            float v1 = c[0][nt][1] + amp0 * c[1][nt][1] + att0 * c[2][nt][1];
            v0 = (v0 + bi.x) * sn0;
            v1 = (v1 + bi.y) * sn0;
            v0 = fmaxf(fmaf(v0, sc0, sh0), 0.f);
            v1 = fmaxf(fmaf(v1, sc1, sh1), 0.f);
            float2 hres = *(const float2*)(h + (size_t)r0 * D + col);
            *(float2*)(out + (size_t)r0 * D + col) =
                make_float2(hres.x + v0, hres.y + v1);
        }
        if (r1 < NN) {
            float v0 = c[0][nt][2] + amp1 * c[1][nt][2] + att1 * c[2][nt][2];
            float v1 = c[0][nt][3] + amp1 * c[1][nt][3] + att1 * c[2][nt][3];
            v0 = (v0 + bi.x) * sn1;
            v1 = (v1 + bi.y) * sn1;
            v0 = fmaxf(fmaf(v0, sc0, sh0), 0.f);
            v1 = fmaxf(fmaf(v1, sc1, sh1), 0.f);
            float2 hres = *(const float2*)(h + (size_t)r1 * D + col);
            *(float2*)(out + (size_t)r1 * D + col) =
                make_float2(hres.x + v0, hres.y + v1);
        }
    }
}

// ---------------- launch ----------------------------------------------------
extern "C" void kernel_launch(void* const* d_in, const int* in_sizes, int n_in,
                              void* d_out, int out_size) {
    const float* h = (const float*)d_in[0];
    const float* eig = (const float*)d_in[1];
    const float* snorm = (const float*)d_in[2];
    const float* W = (const float*)d_in[3];
    const float* bias = (const float*)d_in[4];
    const float* gamma = (const float*)d_in[5];
    const float* beta = (const float*)d_in[6];
    const float* mean = (const float*)d_in[7];
    const float* var = (const float*)d_in[8];
    const int* esrc = (const int*)d_in[9];
    const int* edst = (const int*)d_in[10];
    float* out = (float*)d_out;

    // Host-side, non-stream, idempotent: capture-safe (no guard).
    cudaFuncSetAttribute(k_gemm, cudaFuncAttributeMaxDynamicSharedMemorySize,
                         SMEM_BYTES);

    void* cntPtr = nullptr;
    cudaGetSymbolAddress(&cntPtr, g_cnt);
    cudaMemsetAsync(cntPtr, 0, NN * sizeof(int));

    k_prepfill<<<PREPGRID, 256>>>((const int4*)esrc, (const int4*)edst, h, eig, W);
    k_reduce<<<(NN + 7) / 8, 256>>>();
    k_gemm<<<((NN + BM - 1) / BM) * 4, 256, SMEM_BYTES>>>(h, snorm, bias, gamma,
                                                          beta, mean, var, out);
}

// round 11
// speedup vs baseline: 1.0847x; 1.0847x over previous
#include <cuda_runtime.h>
#include <cuda_fp16.h>
#include <math.h>
#include <stdint.h>

#define NN 50000
#define EE 1600000
#define D 128
#define DAGG 384
#define DCAT 1152
#define CAP 128
#define AVG_D_LOG_F 3.4965075614664802f

// ---------------- static scratch --------------------------------------------
__device__ int g_cnt[NN];
__device__ int g_srcl[(size_t)NN * CAP];
__device__ float g_e1[NN];
__device__ __align__(16) __half g_hh[(size_t)NN * D];       // h in fp16
__device__ __align__(16) __half g_aggh[(size_t)NN * DAGG];  // agg fp16 [N,384]
__device__ __align__(16) __half g_Wh[(size_t)DCAT * D];     // W in fp16 [1152,128]

// ---------------- helpers ---------------------------------------------------
__device__ __forceinline__ float4 h4conv(uint2 u) {
    __half2 a = *reinterpret_cast<__half2*>(&u.x);
    __half2 b = *reinterpret_cast<__half2*>(&u.y);
    float2 fa = __half22float2(a);
    float2 fb = __half22float2(b);
    return make_float4(fa.x, fa.y, fb.x, fb.y);
}

__device__ __forceinline__ uint2 pack4(float4 v) {
    uint2 r;
    __half2 lo = __floats2half2_rn(v.x, v.y);
    __half2 hi = __floats2half2_rn(v.z, v.w);
    r.x = *reinterpret_cast<uint32_t*>(&lo);
    r.y = *reinterpret_cast<uint32_t*>(&hi);
    return r;
}

__device__ __forceinline__ void mma_f16(float* c, const uint32_t* a,
                                        uint32_t b0, uint32_t b1) {
    asm volatile(
        "mma.sync.aligned.m16n8k16.row.col.f32.f16.f16.f32 "
        "{%0,%1,%2,%3}, {%4,%5,%6,%7}, {%8,%9}, {%0,%1,%2,%3};\n"
        : "+f"(c[0]), "+f"(c[1]), "+f"(c[2]), "+f"(c[3])
        : "r"(a[0]), "r"(a[1]), "r"(a[2]), "r"(a[3]), "r"(b0), "r"(b1));
}

__device__ __forceinline__ void ldm_x4(uint32_t* r, uint32_t addr) {
    asm volatile("ldmatrix.sync.aligned.m8n8.x4.shared.b16 {%0,%1,%2,%3}, [%4];"
                 : "=r"(r[0]), "=r"(r[1]), "=r"(r[2]), "=r"(r[3]) : "r"(addr));
}

__device__ __forceinline__ void ldm_x4t(uint32_t* r, uint32_t addr) {
    asm volatile("ldmatrix.sync.aligned.m8n8.x4.trans.shared.b16 {%0,%1,%2,%3}, [%4];"
                 : "=r"(r[0]), "=r"(r[1]), "=r"(r[2]), "=r"(r[3]) : "r"(addr));
}

__device__ __forceinline__ void cp16(uint32_t smem_addr, const void* gptr) {
    asm volatile("cp.async.cg.shared.global [%0], [%1], 16;\n"
                 :: "r"(smem_addr), "l"(gptr));
}

__device__ __forceinline__ uint32_t hscale(uint32_t a, uint32_t coef2) {
    __half2 r = __hmul2(*reinterpret_cast<__half2*>(&a),
                        *reinterpret_cast<__half2*>(&coef2));
    return *reinterpret_cast<uint32_t*>(&r);
}

// ---------------- kernel 1: fused prep + bucket fill (high ILP) --------------
#define FILLB 782     // 200192 threads x 8 edges (2 int4 pairs)
#define HCONVB 1563   // 400128 threads x 4 float4
#define WCONVB 576
#define E1B 196
#define PREPGRID (FILLB + HCONVB + WCONVB + E1B)

__global__ void k_prepfill(const int4* __restrict__ src4, const int4* __restrict__ dst4,
                           const float* __restrict__ h, const float* __restrict__ eig,
                           const float* __restrict__ W) {
    int b = blockIdx.x;
    int t = threadIdx.x;
    if (b < FILLB) {
        int i = b * 256 + t;
        if (i >= 200000) return;
        int4 d0 = dst4[i];
        int4 s0 = src4[i];
        int4 d1 = dst4[i + 200000];
        int4 s1 = src4[i + 200000];
        int p0 = atomicAdd(&g_cnt[d0.x], 1);
        int p1 = atomicAdd(&g_cnt[d0.y], 1);
        int p2 = atomicAdd(&g_cnt[d0.z], 1);
        int p3 = atomicAdd(&g_cnt[d0.w], 1);
        int p4 = atomicAdd(&g_cnt[d1.x], 1);
        int p5 = atomicAdd(&g_cnt[d1.y], 1);
        int p6 = atomicAdd(&g_cnt[d1.z], 1);
        int p7 = atomicAdd(&g_cnt[d1.w], 1);
        g_srcl[(size_t)d0.x * CAP + p0] = s0.x;
        g_srcl[(size_t)d0.y * CAP + p1] = s0.y;
        g_srcl[(size_t)d0.z * CAP + p2] = s0.z;
        g_srcl[(size_t)d0.w * CAP + p3] = s0.w;
        g_srcl[(size_t)d1.x * CAP + p4] = s1.x;
        g_srcl[(size_t)d1.y * CAP + p5] = s1.y;
        g_srcl[(size_t)d1.z * CAP + p6] = s1.z;
        g_srcl[(size_t)d1.w * CAP + p7] = s1.w;
    } else if (b < FILLB + HCONVB) {
        int i = (b - FILLB) * 256 + t;   // 0..400127
        if (i >= 400000) return;
        const float4* h4 = (const float4*)h;
        uint2* o = (uint2*)g_hh;
#pragma unroll
        for (int r = 0; r < 4; r++) {
            int idx = i + r * 400000;    // < 1600000
            float4 v = h4[idx];
            o[idx] = pack4(v);
        }
    } else if (b < FILLB + HCONVB + WCONVB) {
        int idx = (b - FILLB - HCONVB) * 256 + t;
        if (idx < DCAT * D)
            g_Wh[idx] = __float2half(W[idx]);
    } else {
        int idx = (b - FILLB - HCONVB - WCONVB) * 256 + t;
        if (idx < NN) g_e1[idx] = eig[(size_t)idx * 4];
    }
}

// ---------------- kernel 2: warp-per-node reduce (8-edge ILP) ----------------
__global__ __launch_bounds__(256) void k_reduce() {
    int wid = threadIdx.x >> 5;
    int lane = threadIdx.x & 31;
    int node = blockIdx.x * 8 + wid;
    if (node >= NN) return;
    int deg = g_cnt[node];
    size_t base = (size_t)node * CAP;
    float e1d = g_e1[node];
    const uint2* h2 = reinterpret_cast<const uint2*>(g_hh);

    float sx = 0.f, sy = 0.f, sz = 0.f, sw = 0.f;
    float mxx = -3.402823466e38f, mxy = mxx, mxz = mxx, mxw = mxx;
    float dx = 0.f, dy = 0.f, dz = 0.f, dw = 0.f;
    float wsum = 0.f;

    int j = 0;
    for (; j + 8 <= deg; j += 8) {
        int s[8];
        float w[8];
        uint2 u[8];
#pragma unroll
        for (int q = 0; q < 8; q++) s[q] = g_srcl[base + j + q];
#pragma unroll
        for (int q = 0; q < 8; q++) u[q] = h2[(size_t)s[q] * 32 + lane];
#pragma unroll
        for (int q = 0; q < 8; q++) w[q] = fabsf(g_e1[s[q]] - e1d);
#pragma unroll
        for (int q = 0; q < 8; q++) {
            float4 v = h4conv(u[q]);
            sx += v.x; sy += v.y; sz += v.z; sw += v.w;
            mxx = fmaxf(mxx, v.x); mxy = fmaxf(mxy, v.y);
            mxz = fmaxf(mxz, v.z); mxw = fmaxf(mxw, v.w);
            dx = fmaf(w[q], v.x, dx); dy = fmaf(w[q], v.y, dy);
            dz = fmaf(w[q], v.z, dz); dw = fmaf(w[q], v.w, dw);
            wsum += w[q];
        }
    }
    for (; j < deg; j++) {
        int s0 = g_srcl[base + j];
        float w0 = fabsf(g_e1[s0] - e1d);
        float4 v0 = h4conv(h2[(size_t)s0 * 32 + lane]);
        sx += v0.x; sy += v0.y; sz += v0.z; sw += v0.w;
        mxx = fmaxf(mxx, v0.x); mxy = fmaxf(mxy, v0.y);
        mxz = fmaxf(mxz, v0.z); mxw = fmaxf(mxw, v0.w);
        dx = fmaf(w0, v0.x, dx); dy = fmaf(w0, v0.y, dy);
        dz = fmaf(w0, v0.z, dz); dw = fmaf(w0, v0.w, dw);
        wsum += w0;
    }

    float invd = 1.f / (float)(deg > 0 ? deg : 1);
    float invw = 1.f / (wsum + 1e-30f);
    if (deg == 0) { mxx = 0.f; mxy = 0.f; mxz = 0.f; mxw = 0.f; }

    uint2* o = reinterpret_cast<uint2*>(g_aggh) + (size_t)node * 96;
    o[lane]      = pack4(make_float4(sx * invd, sy * invd, sz * invd, sw * invd));
    o[32 + lane] = pack4(make_float4(mxx, mxy, mxz, mxw));
    o[64 + lane] = pack4(make_float4(dx * invw, dy * invw, dz * invw, dw * invw));
}

// ---------------- kernel 3: fused triple-B GEMM, BK=64, 2-stage --------------
// Tile: BM=128 x BN=64; grid = 391 x 2. 6 k-steps of 64, 12 barriers total.
#define BM 128
#define BN 64
#define BK 64
#define NKT (DAGG / BK)  // 6
// byte layout: A stage 128 rows x 144B = 18432; B stage 3 g x 64 rows x 144B = 27648
#define A_STAGE 18432
#define B_OFF (2 * A_STAGE)                 // 36864
#define B_STAGE 27648
#define COEF_OFF (B_OFF + 2 * B_STAGE)      // 92160
#define SMEM_BYTES (COEF_OFF + 3 * 128 * 4) // 93696

__global__ __launch_bounds__(256, 2) void k_gemm(
    const float* __restrict__ h, const float* __restrict__ snorm,
    const float* __restrict__ bias, const float* __restrict__ gamma,
    const float* __restrict__ beta, const float* __restrict__ mean,
    const float* __restrict__ var, float* __restrict__ out) {
    extern __shared__ char smc[];
    uint32_t sb = (uint32_t)__cvta_generic_to_shared(smc);
    float* samp = (float*)(smc + COEF_OFF);
    float* satt = samp + BM;
    float* ssn = satt + BM;

    int tid = threadIdx.x;
    int wid = tid >> 5;
    int lane = tid & 31;
    int t = lane & 3;
    int gid = lane >> 2;
    int wr = wid & 3;   // rows wr*32
    int wc = wid >> 2;  // cols wc*32 (0..1)
    int rowBlock = (blockIdx.x >> 1) * BM;
    int colBlock = (blockIdx.x & 1) * BN;

    // per-row scaler coefficients
    for (int i = tid; i < BM; i += 256) {
        int r = rowBlock + i;
        float amp = 0.f, att = 0.f, sn = 0.f;
        if (r < NN) {
            int deg = g_cnt[r];
            float logD = logf((float)deg + 1.0f);
            amp = logD * (1.0f / AVG_D_LOG_F);
            att = fminf(AVG_D_LOG_F / fmaxf(logD, 1e-6f), 60000.f);
            sn = snorm[r];
        }
        samp[i] = amp;
        satt[i] = att;
        ssn[i] = sn;
    }

    // A cp lanes: 1024 chunks (128 rows x 8 chunks of 8 halfs); 4/thread
    const __half* a_src[4];
    uint32_t a_dst[4];
#pragma unroll
    for (int i = 0; i < 4; i++) {
        int c = tid + 256 * i;
        int row = c >> 3, kc = c & 7;
        int gr = rowBlock + row; if (gr > NN - 1) gr = NN - 1;
        a_src[i] = g_aggh + (size_t)gr * DAGG + kc * 8;
        a_dst[i] = sb + row * 144 + kc * 16;
    }

    // B cp lanes: 1536 chunks over [3 g][64 krows][8 chunks]; 6/thread
    const __half* b_src[6];
    uint32_t b_dst[6];
#pragma unroll
    for (int i = 0; i < 6; i++) {
        int c = tid + 256 * i;
        int g = c >> 9;
        int rem = c & 511;
        int krow = rem >> 3;
        int nc = rem & 7;
        b_src[i] = g_Wh + ((size_t)g * DAGG + krow) * D + colBlock + nc * 8;
        b_dst[i] = sb + B_OFF + g * 9216 + krow * 144 + nc * 16;
    }

    float c[2][4][4];
#pragma unroll
    for (int mt = 0; mt < 2; mt++)
#pragma unroll
        for (int nt = 0; nt < 4; nt++)
#pragma unroll
            for (int k = 0; k < 4; k++) c[mt][nt][k] = 0.f;

    // prologue: stage 0 <- kt 0
#pragma unroll
    for (int i = 0; i < 4; i++) cp16(a_dst[i], a_src[i]);
#pragma unroll
    for (int i = 0; i < 6; i++) cp16(b_dst[i], b_src[i]);
    asm volatile("cp.async.commit_group;\n");

    __syncthreads();  // coef arrays visible

    uint32_t amp2[2][2], att2[2][2];
#pragma unroll
    for (int mt = 0; mt < 2; mt++) {
        int r0 = wr * 32 + mt * 16 + gid;
        __half2 a0 = __float2half2_rn(samp[r0]);
        __half2 a1 = __float2half2_rn(samp[r0 + 8]);
        __half2 t0 = __float2half2_rn(satt[r0]);
        __half2 t1 = __float2half2_rn(satt[r0 + 8]);
        amp2[mt][0] = *reinterpret_cast<uint32_t*>(&a0);
        amp2[mt][1] = *reinterpret_cast<uint32_t*>(&a1);
        att2[mt][0] = *reinterpret_cast<uint32_t*>(&t0);
        att2[mt][1] = *reinterpret_cast<uint32_t*>(&t1);
    }

    // ldmatrix bases (stage 0)
    uint32_t a_lm = sb + (wr * 32 + (lane & 15)) * 144 + ((lane >> 4) << 4);
    uint32_t b_lm = sb + B_OFF + (lane & 15) * 144 + wc * 64 + ((lane >> 4) << 4);

    for (int kt = 0; kt < NKT; kt++) {
        int buf = kt & 1;
        if (kt + 1 < NKT) {
            // prefetch kt+1 into the other stage, then wait for current
            size_t koff = (size_t)(kt + 1) * BK;
            uint32_t ao = (buf ^ 1) * A_STAGE;
#pragma unroll
            for (int i = 0; i < 4; i++) cp16(a_dst[i] + ao, a_src[i] + koff);
            uint32_t bo = (buf ^ 1) * B_STAGE;
#pragma unroll
            for (int i = 0; i < 6; i++) cp16(b_dst[i] + bo, b_src[i] + koff * D);
            asm volatile("cp.async.commit_group;\n");
            asm volatile("cp.async.wait_group 1;\n");
        } else {
            asm volatile("cp.async.wait_group 0;\n");
        }
        __syncthreads();

        uint32_t a_base = a_lm + buf * A_STAGE;
        uint32_t b_base = b_lm + buf * B_STAGE;
#pragma unroll
        for (int ks = 0; ks < 4; ks++) {
            uint32_t a[2][4];
            ldm_x4(a[0], a_base + ks * 32);
            ldm_x4(a[1], a_base + 16 * 144 + ks * 32);
#pragma unroll
            for (int g = 0; g < 3; g++) {
                uint32_t bfr[2][4];
#pragma unroll
                for (int p = 0; p < 2; p++)
                    ldm_x4t(bfr[p], b_base + g * 9216 + ks * 2304 + p * 32);
                uint32_t au[2][4];
#pragma unroll
                for (int mt = 0; mt < 2; mt++) {
                    if (g == 0) {
                        au[mt][0] = a[mt][0]; au[mt][1] = a[mt][1];
                        au[mt][2] = a[mt][2]; au[mt][3] = a[mt][3];
                    } else if (g == 1) {
                        au[mt][0] = hscale(a[mt][0], amp2[mt][0]);
                        au[mt][1] = hscale(a[mt][1], amp2[mt][1]);
                        au[mt][2] = hscale(a[mt][2], amp2[mt][0]);
                        au[mt][3] = hscale(a[mt][3], amp2[mt][1]);
                    } else {
                        au[mt][0] = hscale(a[mt][0], att2[mt][0]);
                        au[mt][1] = hscale(a[mt][1], att2[mt][1]);
                        au[mt][2] = hscale(a[mt][2], att2[mt][0]);
                        au[mt][3] = hscale(a[mt][3], att2[mt][1]);
                    }
                }
#pragma unroll
                for (int p = 0; p < 2; p++) {
#pragma unroll
                    for (int mt = 0; mt < 2; mt++) {
                        mma_f16(c[mt][p * 2], au[mt], bfr[p][0], bfr[p][1]);
                        mma_f16(c[mt][p * 2 + 1], au[mt], bfr[p][2], bfr[p][3]);
                    }
                }
            }
        }
        __syncthreads();
    }

    // fused epilogue
#pragma unroll
    for (int nt = 0; nt < 4; nt++) {
        int col = colBlock + wc * 32 + nt * 8 + 2 * t;
        float2 bi = *(const float2*)(bias + col);
        float2 mn = *(const float2*)(mean + col);
        float2 vr = *(const float2*)(var + col);
        float2 gm = *(const float2*)(gamma + col);
        float2 bt = *(const float2*)(beta + col);
        float sc0 = rsqrtf(vr.x + 1e-5f) * gm.x;
        float sc1 = rsqrtf(vr.y + 1e-5f) * gm.y;
        float sh0 = bt.x - mn.x * sc0;
        float sh1 = bt.y - mn.y * sc1;
#pragma unroll
        for (int mt = 0; mt < 2; mt++) {
#pragma unroll
            for (int p = 0; p < 2; p++) {
                int rloc = wr * 32 + mt * 16 + gid + p * 8;
                int r = rowBlock + rloc;
                if (r < NN) {
                    float sn = ssn[rloc];
                    float v0 = (c[mt][nt][p * 2 + 0] + bi.x) * sn;
                    float v1 = (c[mt][nt][p * 2 + 1] + bi.y) * sn;
                    v0 = fmaxf(fmaf(v0, sc0, sh0), 0.f);
                    v1 = fmaxf(fmaf(v1, sc1, sh1), 0.f);
                    float2 hres = *(const float2*)(h + (size_t)r * D + col);
                    *(float2*)(out + (size_t)r * D + col) =
                        make_float2(hres.x + v0, hres.y + v1);
                }
            }
        }
    }
}

// ---------------- launch ----------------------------------------------------
extern "C" void kernel_launch(void* const* d_in, const int* in_sizes, int n_in,
                              void* d_out, int out_size) {
    const float* h = (const float*)d_in[0];
    const float* eig = (const float*)d_in[1];
    const float* snorm = (const float*)d_in[2];
    const float* W = (const float*)d_in[3];
    const float* bias = (const float*)d_in[4];
    const float* gamma = (const float*)d_in[5];
    const float* beta = (const float*)d_in[6];
    const float* mean = (const float*)d_in[7];
    const float* var = (const float*)d_in[8];
    const int* esrc = (const int*)d_in[9];
    const int* edst = (const int*)d_in[10];
    float* out = (float*)d_out;

    // Host-side, non-stream, idempotent: capture-safe (no guard).
    cudaFuncSetAttribute(k_gemm, cudaFuncAttributeMaxDynamicSharedMemorySize,
                         SMEM_BYTES);

    void* cntPtr = nullptr;
    cudaGetSymbolAddress(&cntPtr, g_cnt);
    cudaMemsetAsync(cntPtr, 0, NN * sizeof(int));

    k_prepfill<<<PREPGRID, 256>>>((const int4*)esrc, (const int4*)edst, h, eig, W);
    k_reduce<<<(NN + 7) / 8, 256>>>();
    k_gemm<<<((NN + BM - 1) / BM) * 2, 256, SMEM_BYTES>>>(h, snorm, bias, gamma,
                                                          beta, mean, var, out);
}